// round 1
// baseline (speedup 1.0000x reference)
#include <cuda_runtime.h>
#include <cstddef>

// ChebychevTransform: x[8,256,256,8] f32 -> out[8,256,256,128] f32
// out[b,h,w, c*16 + p*4 + k] = sum_{i,j in 0..3} T[p,j]*T[k,i] * x[b,h+i-1,w+j-1,c]
// (zero-padded outside), with the n=4 Chebyshev/DCT-I matrix
//   T = [[1/6, 1/3, 1/3, 1/6],
//        [1/3, 1/3,-1/3,-1/3],
//        [1/3,-1/3,-1/3, 1/3],
//        [1/3,-2/3, 2/3,-1/3]]

#define HH 256
#define WW 256
#define CC 8

// 4-point Chebyshev transform via even/odd butterfly (12 flops vs 16 FMA).
__device__ __forceinline__ void cheb4(float x0, float x1, float x2, float x3,
                                      float& y0, float& y1, float& y2, float& y3) {
    const float K3 = 1.0f / 3.0f;
    const float K6 = 1.0f / 6.0f;
    float s0 = x0 + x3;
    float s1 = x1 + x2;
    float d0 = x0 - x3;
    float d1 = x1 - x2;
    y0 = fmaf(s1, K3, s0 * K6);       // s0/6 + s1/3
    y1 = (d0 + d1) * K3;              // (d0+d1)/3
    y2 = (s0 - s1) * K3;              // (s0-s1)/3
    y3 = fmaf(d1, -2.0f, d0) * K3;    // (d0 - 2*d1)/3
}

__global__ __launch_bounds__(256)
void cheb_kernel(const float* __restrict__ x, float* __restrict__ out) {
    // thread = (pixel, channel); c fastest for coalescing
    int gid = blockIdx.x * 256 + threadIdx.x;   // 0 .. 4194303
    int c   = gid & (CC - 1);
    int pix = gid >> 3;                          // b*H*W + h*W + w
    int w   = pix & (WW - 1);
    int h   = (pix >> 8) & (HH - 1);
    int b   = pix >> 16;

    const float* base = x + ((size_t)b * HH * WW) * CC + c;

    float r[4][4];
    if (h >= 1 && h <= HH - 3 && w >= 1 && w <= WW - 3) {
        // interior fast path: unguarded coalesced loads
        #pragma unroll
        for (int i = 0; i < 4; i++) {
            const float* p = base + (size_t)((h + i - 1) * WW + (w - 1)) * CC;
            r[i][0] = p[0 * CC];
            r[i][1] = p[1 * CC];
            r[i][2] = p[2 * CC];
            r[i][3] = p[3 * CC];
        }
    } else {
        #pragma unroll
        for (int i = 0; i < 4; i++) {
            int hi = h + i - 1;
            #pragma unroll
            for (int j = 0; j < 4; j++) {
                int wj = w + j - 1;
                bool ok = (hi >= 0) && (hi < HH) && (wj >= 0) && (wj < WW);
                r[i][j] = ok ? base[(size_t)(hi * WW + wj) * CC] : 0.0f;
            }
        }
    }

    // horizontal transform over j: u[i][p] = sum_j T[p,j] * r[i][j]
    float u[4][4];
    #pragma unroll
    for (int i = 0; i < 4; i++) {
        cheb4(r[i][0], r[i][1], r[i][2], r[i][3],
              u[i][0], u[i][1], u[i][2], u[i][3]);
    }

    // vertical transform over i for each p, then vectorized store:
    // out channel layout = c*16 + p*4 + k  -> one float4 per p
    float4* op = (float4*)(out + (size_t)pix * 128 + c * 16);
    #pragma unroll
    for (int p = 0; p < 4; p++) {
        float4 o;
        cheb4(u[0][p], u[1][p], u[2][p], u[3][p], o.x, o.y, o.z, o.w);
        op[p] = o;
    }
}

extern "C" void kernel_launch(void* const* d_in, const int* in_sizes, int n_in,
                              void* d_out, int out_size) {
    const float* x = (const float*)d_in[0];
    float* out = (float*)d_out;
    // 8*256*256*8 threads = 4,194,304 -> 16384 blocks of 256
    cheb_kernel<<<16384, 256>>>(x, out);
}

// round 3
// speedup vs baseline: 1.2187x; 1.2187x over previous
#include <cuda_runtime.h>
#include <cstddef>

// ChebychevTransform: x[8,256,256,8] f32 -> out[8,256,256,128] f32
// out[b,h,w, c*16 + p*4 + k] = sum_{i,j} T[p,j]*T[k,i]*x[b,h+i-1,w+j-1,c] (zero pad)
// T = [[1/6,1/3,1/3,1/6],[1/3,1/3,-1/3,-1/3],[1/3,-1/3,-1/3,1/3],[1/3,-2/3,2/3,-1/3]]
//
// Warp layout: one warp = one (b, h-strip of 8, w) column.
// lane = (c = lane>>2, p = lane&3): lane computes the float4 (k=0..3) that lands
// at byte offset lane*16 of each pixel's 512B output block -> 4 dense STG.128/pixel.

#define HH 256
#define WW 256
#define CC 8
#define SS 8   // pixels per warp along h

// vertical 4-point Chebyshev butterfly (k = 0..3 outputs)
__device__ __forceinline__ void cheb4(float x0, float x1, float x2, float x3,
                                      float& y0, float& y1, float& y2, float& y3) {
    const float K3 = 1.0f / 3.0f;
    const float K6 = 1.0f / 6.0f;
    float s0 = x0 + x3, s1 = x1 + x2;
    float d0 = x0 - x3, d1 = x1 - x2;
    y0 = fmaf(s1, K3, s0 * K6);
    y1 = (d0 + d1) * K3;
    y2 = (s0 - s1) * K3;
    y3 = fmaf(d1, -2.0f, d0) * K3;
}

__global__ __launch_bounds__(256)
void cheb_kernel(const float* __restrict__ x, float* __restrict__ out) {
    int tid  = blockIdx.x * 256 + threadIdx.x;
    int lane = tid & 31;
    int wid  = tid >> 5;                 // 65536 warps total
    int w    = wid & (WW - 1);
    int hs   = (wid >> 8) & 31;          // 32 strips of 8 rows
    int b    = wid >> 13;
    int h0   = hs * SS;

    int c = lane >> 2;
    int p = lane & 3;

    // lane's horizontal Chebyshev row T[p,:]
    const float K3 = 1.0f / 3.0f, K6 = 1.0f / 6.0f, K23 = 2.0f / 3.0f;
    float a0 = (p == 0) ? K6 : K3;
    float a1 = (p <= 1) ? K3 : (p == 2 ? -K3 : -K23);
    float a2 = (p == 0) ? K3 : (p == 3 ? K23 : -K3);
    float a3 = (p == 0) ? K6 : (p == 2 ? K3 : -K3);

    // column-base pointer at (b, row 0, w-1, c); only valid offsets dereferenced
    const float* base = x + ((size_t)b * HH * WW + (w - 1)) * CC + c;
    bool v0 = (w >= 1);
    bool v2 = (w + 1 < WW);
    bool v3 = (w + 2 < WW);

    float ring[4];
    float* outp = out + ((size_t)(b * HH + h0) * WW + w) * (CC * 16) + lane * 4;

    #pragma unroll
    for (int t = 0; t < SS + 3; t++) {
        int r = h0 - 1 + t;
        float u;
        if (r >= 0 && r < HH) {
            const float* rp = base + (size_t)r * (WW * CC);
            float x0 = v0 ? rp[0]      : 0.0f;
            float x1 =      rp[CC];
            float x2 = v2 ? rp[2 * CC] : 0.0f;
            float x3 = v3 ? rp[3 * CC] : 0.0f;
            u = fmaf(a0, x0, fmaf(a1, x1, fmaf(a2, x2, a3 * x3)));
        } else {
            u = 0.0f;
        }
        ring[t & 3] = u;
        if (t >= 3) {
            float4 o;
            cheb4(ring[(t - 3) & 3], ring[(t - 2) & 3],
                  ring[(t - 1) & 3], ring[t & 3],
                  o.x, o.y, o.z, o.w);
            *(float4*)outp = o;                  // dense: lane l -> byte l*16
            outp += (size_t)WW * CC * 16;        // next output row
        }
    }
}

extern "C" void kernel_launch(void* const* d_in, const int* in_sizes, int n_in,
                              void* d_out, int out_size) {
    const float* x = (const float*)d_in[0];
    float* out = (float*)d_out;
    // 65536 warps * 32 = 2,097,152 threads -> 8192 blocks of 256
    cheb_kernel<<<8192, 256>>>(x, out);
}

// round 5
// speedup vs baseline: 1.5455x; 1.2681x over previous
#include <cuda_runtime.h>
#include <cstddef>

// ChebychevTransform: x[8,256,256,8] f32 -> out[8,256,256,128] f32
// out[b,h,w, c*16 + p*4 + k] = sum_{i,j} T[p,j]*T[k,i]*x[b,h+i-1,w+j-1,c] (zero pad:
// 1 row/col before, 2 after, per TF SAME with n=4)
// T = [[1/6,1/3,1/3,1/6],[1/3,1/3,-1/3,-1/3],[1/3,-1/3,-1/3,1/3],[1/3,-2/3,2/3,-1/3]]
//
// Warp = one (b, w, 8-row strip). lane = (c=lane>>2, p=lane&3): lane produces the
// float4 (k=0..3) at byte offset lane*16 of each pixel's 512B block -> dense STG.128.
// All 44 stencil loads prefetched into registers (MLP ~44); row index clamped with
// min/max so every address is in-bounds; padding rows zeroed after the transform.

#define HH 256
#define WW 256
#define CC 8
#define SS 8   // pixels per warp along h
#define NR (SS + 3)

__device__ __forceinline__ void cheb4(float x0, float x1, float x2, float x3,
                                      float& y0, float& y1, float& y2, float& y3) {
    const float K3 = 1.0f / 3.0f;
    const float K6 = 1.0f / 6.0f;
    float s0 = x0 + x3, s1 = x1 + x2;
    float d0 = x0 - x3, d1 = x1 - x2;
    y0 = fmaf(s1, K3, s0 * K6);
    y1 = (d0 + d1) * K3;
    y2 = (s0 - s1) * K3;
    y3 = fmaf(d1, -2.0f, d0) * K3;
}

__global__ __launch_bounds__(256)
void cheb_kernel(const float* __restrict__ x, float* __restrict__ out) {
    int tid  = blockIdx.x * 256 + threadIdx.x;
    int lane = tid & 31;
    int wid  = tid >> 5;                 // 65536 warps
    int w    = wid & (WW - 1);
    int hs   = (wid >> 8) & 31;          // 32 strips of 8 rows
    int b    = wid >> 13;
    int h0   = hs * SS;

    int c = lane >> 2;
    int p = lane & 3;

    // lane's horizontal Chebyshev row T[p,:]
    const float K3 = 1.0f / 3.0f, K6 = 1.0f / 6.0f, K23 = 2.0f / 3.0f;
    float a0 = (p == 0) ? K6 : K3;
    float a1 = (p <= 1) ? K3 : (p == 2 ? -K3 : -K23);
    float a2 = (p == 0) ? K3 : (p == 3 ? K23 : -K3);
    float a3 = (p == 0) ? K6 : (p == 2 ? K3 : -K3);

    const float* base = x + ((size_t)b * HH * WW + (w - 1)) * CC + c;
    bool v0 = (w >= 1);
    bool v2 = (w + 1 < WW);
    bool v3 = (w + 2 < WW);

    // ---- prefetch phase: 44 independent loads, clamped row addressing ----
    float xv[NR][4];
    #pragma unroll
    for (int t = 0; t < NR; t++) {
        int r  = h0 - 1 + t;                   // true stencil row (-1 .. 257)
        int rc = min(max(r, 0), HH - 1);       // clamped, always in-bounds
        const float* rp = base + (size_t)rc * (WW * CC);
        xv[t][0] = v0 ? rp[0]      : 0.0f;
        xv[t][1] =      rp[CC];
        xv[t][2] = v2 ? rp[2 * CC] : 0.0f;
        xv[t][3] = v3 ? rp[3 * CC] : 0.0f;
    }

    // ---- horizontal transform per row; zero padding rows ----
    float u[NR];
    #pragma unroll
    for (int t = 0; t < NR; t++) {
        int r = h0 - 1 + t;
        float v = fmaf(a0, xv[t][0], fmaf(a1, xv[t][1],
                  fmaf(a2, xv[t][2], a3 * xv[t][3])));
        u[t] = (r >= 0 && r < HH) ? v : 0.0f;
    }

    // ---- vertical butterflies + dense stores ----
    float* outp = out + ((size_t)(b * HH + h0) * WW + w) * (CC * 16) + lane * 4;
    #pragma unroll
    for (int s = 0; s < SS; s++) {
        float4 o;
        cheb4(u[s], u[s + 1], u[s + 2], u[s + 3], o.x, o.y, o.z, o.w);
        *(float4*)(outp + (size_t)s * (WW * CC * 16)) = o;
    }
}

extern "C" void kernel_launch(void* const* d_in, const int* in_sizes, int n_in,
                              void* d_out, int out_size) {
    const float* x = (const float*)d_in[0];
    float* out = (float*)d_out;
    cheb_kernel<<<8192, 256>>>(x, out);
}

// round 6
// speedup vs baseline: 1.6197x; 1.0480x over previous
#include <cuda_runtime.h>
#include <cstddef>

// ChebychevTransform: x[8,256,256,8] f32 -> out[8,256,256,128] f32
// out[b,h,w, c*16 + p*4 + k] = sum_{i,j} T[p,j]*T[k,i]*x[b,h+i-1,w+j-1,c] (zero pad:
// 1 before / 2 after, TF SAME n=4)
// T = [[1/6,1/3,1/3,1/6],[1/3,1/3,-1/3,-1/3],[1/3,-1/3,-1/3,1/3],[1/3,-2/3,2/3,-1/3]]
//
// Warp = one (b, w, 8-row strip).
// Load phase:  lane = (j=lane>>3, c=lane&7) -> one coalesced 128B LDG per row
//              (the 32 floats x[row, w-1..w+2, 0..7]).
// Horizontal transform in-warp via butterfly shuffles:
//   stage1 (xor 24): pairs j with 3-j  -> {s0, s1, -d1, -d0}
//   stage2 (xor 8):  pairs within      -> u[p] with p = bitrev2(j)
// Vertical transform per lane (register ring over 11 rows), then dense STG.128:
// lane writes float4 at byte offset (c*16 + p*4)*4 of the pixel's 512B block.

#define HH 256
#define WW 256
#define CC 8
#define SS 8
#define NR (SS + 3)

__device__ __forceinline__ void cheb4(float x0, float x1, float x2, float x3,
                                      float& y0, float& y1, float& y2, float& y3) {
    const float K3 = 1.0f / 3.0f;
    const float K6 = 1.0f / 6.0f;
    float s0 = x0 + x3, s1 = x1 + x2;
    float d0 = x0 - x3, d1 = x1 - x2;
    y0 = fmaf(s1, K3, s0 * K6);
    y1 = (d0 + d1) * K3;
    y2 = (s0 - s1) * K3;
    y3 = fmaf(d1, -2.0f, d0) * K3;
}

__global__ __launch_bounds__(256)
void cheb_kernel(const float* __restrict__ x, float* __restrict__ out) {
    const unsigned FULL = 0xffffffffu;
    int tid  = blockIdx.x * 256 + threadIdx.x;
    int lane = tid & 31;
    int wid  = tid >> 5;                 // 65536 warps
    int w    = wid & (WW - 1);
    int hs   = (wid >> 8) & 31;          // 32 strips of 8 rows
    int b    = wid >> 13;
    int h0   = hs * SS;

    int j  = lane >> 3;                  // horizontal tap 0..3
    int cl = lane & 7;                   // channel 0..7

    // lane's load column (clamped) + validity for the w edges
    int wj  = w - 1 + j;
    bool wv = (wj >= 0) && (wj < WW);
    int cw  = min(max(wj, 0), WW - 1);
    const float* lbase = x + ((size_t)b * HH * WW + cw) * CC + cl;

    // ---- load phase: 11 coalesced 128B LDGs, clamped rows ----
    float raw[NR];
    #pragma unroll
    for (int t = 0; t < NR; t++) {
        int rc = min(max(h0 - 1 + t, 0), HH - 1);
        float v = lbase[(size_t)rc * (WW * CC)];
        raw[t] = wv ? v : 0.0f;
    }

    // ---- horizontal transform via butterfly shuffles ----
    const float K3 = 1.0f / 3.0f, K6 = 1.0f / 6.0f, K23 = 2.0f / 3.0f;
    float ca = (j == 0) ? K6 : -K3;
    float cb = (j == 3) ? K23 : ((j == 2) ? -K3 : K3);

    float u[NR];
    #pragma unroll
    for (int t = 0; t < NR; t++) {
        float s  = __shfl_xor_sync(FULL, raw[t], 24);
        float av = (j < 2) ? (raw[t] + s) : (raw[t] - s);
        float bv = __shfl_xor_sync(FULL, av, 8);
        float uu = fmaf(ca, av, cb * bv);
        int r = h0 - 1 + t;
        u[t] = (r >= 0 && r < HH) ? uu : 0.0f;   // vertical zero-padding rows
    }

    // ---- vertical butterflies + dense stores ----
    int p = ((j & 1) << 1) | (j >> 1);           // bitrev2: lane's output row p
    float* outp = out + ((size_t)(b * HH + h0) * WW + w) * (CC * 16)
                      + (cl * 16 + p * 4);
    #pragma unroll
    for (int s = 0; s < SS; s++) {
        float4 o;
        cheb4(u[s], u[s + 1], u[s + 2], u[s + 3], o.x, o.y, o.z, o.w);
        *(float4*)(outp + (size_t)s * (WW * CC * 16)) = o;
    }
}

extern "C" void kernel_launch(void* const* d_in, const int* in_sizes, int n_in,
                              void* d_out, int out_size) {
    const float* x = (const float*)d_in[0];
    float* out = (float*)d_out;
    cheb_kernel<<<8192, 256>>>(x, out);
}